// round 14
// baseline (speedup 1.0000x reference)
#include <cuda_runtime.h>

// ---------------------------------------------------------------------------
// Linformer block via mma.sync tf32 (HMMA; compute_103 PTX target).
// R14: 128x256 CTA tile, 8 warps as 2m x 4n => 64x64 warp tile (halves smem
// crossbar bytes per MAC), 3-stage cp.async, 1 barrier/chunk, LDSM.x4.
// 1 CTA/SM, ~190 regs. Middle kernels unchanged.
// ---------------------------------------------------------------------------

#define BDIM  8192
#define NTOK  4
#define CDIM  1024
#define HDIM  16
#define DDIM  64
#define PDIM  4
#define MTOK  (BDIM * NTOK)
#define SCALE_F 0.125f

__device__ float g_qkv[(size_t)MTOK * 3 * CDIM];
__device__ float g_ctx[(size_t)MTOK * CDIM];
__device__ float g_xtf[(size_t)MTOK * CDIM];
__device__ float g_Wt [(size_t)3 * CDIM * CDIM];
__device__ float g_Wpt[(size_t)CDIM * CDIM];

// ------------------------------ GEMM config --------------------------------
#define BM 128
#define BN 256
#define BKC 32
#define NCH (CDIM / BKC)
#define RS 36                              // 144B rows: LDSM/STS conflict-free
#define STAGE_ROWS (BM + BN)               // 384
#define STAGE_FLOATS (STAGE_ROWS * RS)
#define STAGE_BYTES  (STAGE_FLOATS * 4)    // 55296
#define NSTAGE 3
#define SMEM_DYN (NSTAGE * STAGE_BYTES)    // 165888

__device__ __forceinline__ unsigned smem_u32(const void* p) {
    unsigned a;
    asm("{ .reg .u64 t; cvta.to.shared.u64 t, %1; cvt.u32.u64 %0, t; }"
        : "=r"(a) : "l"(p));
    return a;
}
__device__ __forceinline__ void cp16(unsigned saddr, const float* g) {
    asm volatile("cp.async.cg.shared.global [%0], [%1], 16;"
                 :: "r"(saddr), "l"(g) : "memory");
}
__device__ __forceinline__ void cp_commit() {
    asm volatile("cp.async.commit_group;" ::: "memory");
}
template<int N_>
__device__ __forceinline__ void cp_wait() {
    asm volatile("cp.async.wait_group %0;" :: "n"(N_) : "memory");
}
__device__ __forceinline__ unsigned f2tf(float f) {
    unsigned u; asm("cvt.rna.tf32.f32 %0, %1;" : "=r"(u) : "f"(f)); return u;
}
__device__ __forceinline__ float f2tf_f(float f) {
    return __uint_as_float(f2tf(f));
}
__device__ __forceinline__ void ldsm4(unsigned& r0, unsigned& r1,
                                      unsigned& r2, unsigned& r3, unsigned a) {
    asm volatile("ldmatrix.sync.aligned.m8n8.x4.shared.b16 {%0,%1,%2,%3}, [%4];"
                 : "=r"(r0), "=r"(r1), "=r"(r2), "=r"(r3) : "r"(a));
}
__device__ __forceinline__ void mma_tf32(float* d, const unsigned* a,
                                         const unsigned* b) {
    asm volatile(
        "mma.sync.aligned.m16n8k8.row.col.f32.tf32.tf32.f32 "
        "{%0,%1,%2,%3}, {%4,%5,%6,%7}, {%8,%9}, {%0,%1,%2,%3};"
        : "+f"(d[0]), "+f"(d[1]), "+f"(d[2]), "+f"(d[3])
        : "r"(a[0]), "r"(a[1]), "r"(a[2]), "r"(a[3]), "r"(b[0]), "r"(b[1]));
}

// ---------------------------------------------------------------------------
// C[M,Ncols] = A[M,1024] * B^T (+bias); A,B pre-rounded tf32.
// 128x256 tile, 8 warps (2m x 4n), warp tile 64x64, 3-stage cp.async.
// ---------------------------------------------------------------------------
template<bool BIAS>
__global__ __launch_bounds__(256, 1)
void tf32_gemm(const float* __restrict__ A, const float* __restrict__ B,
               const float* __restrict__ bias, float* __restrict__ C, int Ncols)
{
    extern __shared__ float smf[];
    const unsigned sb = smem_u32(smf);
    const int tid = threadIdx.x;
    const int m0 = blockIdx.y * BM;
    const int n0 = blockIdx.x * BN;

    const int w  = tid >> 5;
    const int wm = w & 1;              // 0..1 -> m offset wm*64
    const int wn = w >> 1;             // 0..3 -> n offset wn*64
    const int ln = tid & 31;
    const int g  = ln >> 2;
    const int q  = ln & 3;

    // cp.async: A 1024 segs (4/thread), B 2048 segs (8/thread, derive +4 slots)
    const float* gA[4]; unsigned sA[4];
    const float* gB[4]; unsigned sB[4];
    #pragma unroll
    for (int i = 0; i < 4; i++) {
        int idx = tid + i * 256;
        int row = idx >> 3, seg = idx & 7;
        gA[i] = A + (size_t)(m0 + row) * CDIM + seg * 4;
        sA[i] = sb + (row * RS + seg * 4) * 4;
        gB[i] = B + (size_t)(n0 + row) * CDIM + seg * 4;     // rows 0..127
        sB[i] = sb + ((BM + row) * RS + seg * 4) * 4;
    }

    #define ISSUE(ch) do { unsigned so = ((ch) % NSTAGE) * STAGE_BYTES;       \
        int ko = (ch) * BKC;                                                  \
        _Pragma("unroll") for (int i = 0; i < 4; i++) {                       \
            cp16(sA[i] + so, gA[i] + ko);                                     \
            cp16(sB[i] + so, gB[i] + ko);                                     \
            cp16(sB[i] + so + 128 * RS * 4, gB[i] + ko + (size_t)128 * CDIM); } \
        cp_commit(); } while (0)

    float acc[4][8][4];
    #pragma unroll
    for (int mi = 0; mi < 4; mi++)
        #pragma unroll
        for (int nf = 0; nf < 8; nf++)
            #pragma unroll
            for (int i = 0; i < 4; i++) acc[mi][nf][i] = 0.f;

    ISSUE(0);
    ISSUE(1);

    // LDSM lane bases (stage 0, kk=0)
    const unsigned aA = sb + ((wm * 64 + (ln & 15)) * RS) * 4
                        + ((ln & 16) ? 16 : 0);
    const unsigned aB = sb + ((BM + wn * 64 + (ln & 7) + ((ln & 16) ? 8 : 0)) * RS) * 4
                        + ((ln & 8) ? 16 : 0);

    for (int s = 0; s < NCH; s++) {
        if (s < NCH - 1) cp_wait<1>(); else cp_wait<0>();
        __syncthreads();
        if (s + 2 < NCH) ISSUE(s + 2);   // stage (s+2)%3 last read at chunk s-1

        const unsigned sof = (s % NSTAGE) * STAGE_BYTES;

        #pragma unroll
        for (int kk = 0; kk < 4; kk++) {
            const unsigned ko = sof + kk * 32;
            unsigned am[4][4], br[4][4];
            #pragma unroll
            for (int mi = 0; mi < 4; mi++)
                ldsm4(am[mi][0], am[mi][1], am[mi][2], am[mi][3],
                      aA + ko + mi * (16 * RS * 4));
            #pragma unroll
            for (int j = 0; j < 4; j++)
                ldsm4(br[j][0], br[j][1], br[j][2], br[j][3],
                      aB + ko + j * (16 * RS * 4));
            #pragma unroll
            for (int mi = 0; mi < 4; mi++)
                #pragma unroll
                for (int j = 0; j < 4; j++) {
                    mma_tf32(acc[mi][2 * j],     am[mi], &br[j][0]);
                    mma_tf32(acc[mi][2 * j + 1], am[mi], &br[j][2]);
                }
        }
    }

    // Epilogue: lane (g,q); rows mw+mi*16 (+8), cols nw+nf*8
    const int mw = m0 + wm * 64 + g;
    const int nw = n0 + wn * 64 + 2 * q;
    #pragma unroll
    for (int mi = 0; mi < 4; mi++) {
        #pragma unroll
        for (int nf = 0; nf < 8; nf++) {
            int col = nw + nf * 8;
            float b0 = 0.f, b1 = 0.f;
            if (BIAS) { b0 = __ldg(bias + col); b1 = __ldg(bias + col + 1); }
            float* p0 = C + (size_t)(mw + mi * 16) * Ncols + col;
            float* p1 = p0 + (size_t)8 * Ncols;
            p0[0] = acc[mi][nf][0] + b0;  p0[1] = acc[mi][nf][1] + b1;
            p1[0] = acc[mi][nf][2] + b0;  p1[1] = acc[mi][nf][3] + b1;
        }
    }
    #undef ISSUE
}

// ---------------------------------------------------------------------------
// W_qkv transpose + tf32 round
// ---------------------------------------------------------------------------
__global__ __launch_bounds__(256)
void transpose_kernel(const float* __restrict__ in, float* __restrict__ out)
{
    __shared__ float t[32][33];
    int bx = blockIdx.x * 32, by = blockIdx.y * 32;
    int x = threadIdx.x & 31, y = threadIdx.x >> 5;
    #pragma unroll
    for (int i = 0; i < 32; i += 8)
        t[y + i][x] = f2tf_f(in[(size_t)(by + y + i) * (3 * CDIM) + bx + x]);
    __syncthreads();
    #pragma unroll
    for (int i = 0; i < 32; i += 8)
        out[(size_t)(bx + y + i) * CDIM + by + x] = t[x][y + i];
}

__global__ __launch_bounds__(256)
void round_kernel(const float4* __restrict__ in, float4* __restrict__ out, int n4)
{
    for (int i = blockIdx.x * blockDim.x + threadIdx.x; i < n4;
         i += gridDim.x * blockDim.x) {
        float4 v = in[i];
        v.x = f2tf_f(v.x); v.y = f2tf_f(v.y);
        v.z = f2tf_f(v.z); v.w = f2tf_f(v.w);
        out[i] = v;
    }
}

// ---------------------------------------------------------------------------
// Middle main: one warp per (b,h); lane owns d = {2*lane, 2*lane+1}.
// ---------------------------------------------------------------------------
__global__ __launch_bounds__(256)
void attn_core_kernel(const float* __restrict__ W_E, const float* __restrict__ W_F)
{
    const int wglob = blockIdx.x * 8 + (threadIdx.x >> 5);
    const int b = wglob >> 4;
    const int h = wglob & 15;
    const int lane = threadIdx.x & 31;

    const float* base = g_qkv + (size_t)b * NTOK * 3 * CDIM + h * DDIM + 2 * lane;

    float2 qv[NTOK], kv[NTOK], vv[NTOK];
    #pragma unroll
    for (int n = 0; n < NTOK; n++) {
        const float* r = base + (size_t)n * 3 * CDIM;
        qv[n] = *reinterpret_cast<const float2*>(r);
        kv[n] = *reinterpret_cast<const float2*>(r + CDIM);
        vv[n] = *reinterpret_cast<const float2*>(r + 2 * CDIM);
    }

    float we[16], wf[16];
    #pragma unroll
    for (int i = 0; i < 16; i++) { we[i] = __ldg(W_E + i); wf[i] = __ldg(W_F + i); }

    float2 kl[PDIM], vl[PDIM];
    #pragma unroll
    for (int p = 0; p < PDIM; p++) {
        kl[p].x = kl[p].y = vl[p].x = vl[p].y = 0.f;
        #pragma unroll
        for (int n = 0; n < NTOK; n++) {
            kl[p].x += kv[n].x * we[p * 4 + n];
            kl[p].y += kv[n].y * we[p * 4 + n];
            vl[p].x += vv[n].x * wf[p * 4 + n];
            vl[p].y += vv[n].y * wf[p * 4 + n];
        }
    }

    float lg[16];
    #pragma unroll
    for (int n = 0; n < NTOK; n++)
        #pragma unroll
        for (int p = 0; p < PDIM; p++)
            lg[n * 4 + p] = qv[n].x * kl[p].x + qv[n].y * kl[p].y;
    #pragma unroll
    for (int off = 16; off >= 1; off >>= 1)
        #pragma unroll
        for (int i = 0; i < 16; i++)
            lg[i] += __shfl_xor_sync(0xFFFFFFFFu, lg[i], off);

    float aw[16];
    #pragma unroll
    for (int n = 0; n < NTOK; n++) {
        float l0 = lg[n * 4] * SCALE_F, l1 = lg[n * 4 + 1] * SCALE_F;
        float l2 = lg[n * 4 + 2] * SCALE_F, l3 = lg[n * 4 + 3] * SCALE_F;
        float mx = fmaxf(fmaxf(l0, l1), fmaxf(l2, l3));
        float e0 = __expf(l0 - mx), e1 = __expf(l1 - mx);
        float e2 = __expf(l2 - mx), e3 = __expf(l3 - mx);
        float inv = 1.f / (e0 + e1 + e2 + e3);
        aw[n * 4] = e0 * inv; aw[n * 4 + 1] = e1 * inv;
        aw[n * 4 + 2] = e2 * inv; aw[n * 4 + 3] = e3 * inv;
    }

    float* cbase = g_ctx + (size_t)b * NTOK * CDIM + h * DDIM + 2 * lane;
    #pragma unroll
    for (int n = 0; n < NTOK; n++) {
        float ox = 0.f, oy = 0.f;
        #pragma unroll
        for (int p = 0; p < PDIM; p++) {
            ox += aw[n * 4 + p] * vl[p].x;
            oy += aw[n * 4 + p] * vl[p].y;
        }
        float2 o; o.x = f2tf_f(ox); o.y = f2tf_f(oy);
        *reinterpret_cast<float2*>(cbase + (size_t)n * CDIM) = o;
    }
}

// ---------------------------------------------------------------------------
// attn_sel: one warp per (b,h)
// ---------------------------------------------------------------------------
__global__ __launch_bounds__(256)
void attn_sel_kernel(float* __restrict__ attn_sel)
{
    const int wglob = blockIdx.x * 8 + (threadIdx.x >> 5);
    const int b = wglob >> 4;
    const int h = wglob & 15;
    const int lane = threadIdx.x & 31;

    const float* base = g_qkv + (size_t)b * NTOK * 3 * CDIM;
    float2 qv = *reinterpret_cast<const float2*>(
        base + (size_t)1 * 3 * CDIM + h * DDIM + 2 * lane);

    const float* k2 = base + (size_t)2 * 3 * CDIM + CDIM + 2 * lane;
    float s[16];
    #pragma unroll
    for (int gg = 0; gg < 16; gg++) {
        float2 kv = *reinterpret_cast<const float2*>(k2 + gg * DDIM);
        s[gg] = qv.x * kv.x + qv.y * kv.y;
    }
    #pragma unroll
    for (int off = 16; off >= 1; off >>= 1)
        #pragma unroll
        for (int i = 0; i < 16; i++)
            s[i] += __shfl_xor_sync(0xFFFFFFFFu, s[i], off);

    if (lane < 16) {
        float v = s[lane] * SCALE_F;
        attn_sel[((size_t)b * HDIM + h) * HDIM + lane] = 1.f / (1.f + __expf(-v));
    }
}

// ---------------------------------------------------------------------------
extern "C" void kernel_launch(void* const* d_in, const int* in_sizes, int n_in,
                              void* d_out, int out_size)
{
    (void)in_sizes; (void)n_in; (void)out_size;
    const float* x      = (const float*)d_in[0];
    const float* W_qkv  = (const float*)d_in[1];
    const float* W_proj = (const float*)d_in[2];
    const float* b_proj = (const float*)d_in[3];
    const float* W_E    = (const float*)d_in[4];
    const float* W_F    = (const float*)d_in[5];

    float* out      = (float*)d_out;
    float* attn_sel = out + (size_t)MTOK * CDIM;

    float *qkv_ptr, *ctx_ptr, *xtf_ptr, *wt_ptr, *wpt_ptr;
    cudaGetSymbolAddress((void**)&qkv_ptr, g_qkv);
    cudaGetSymbolAddress((void**)&ctx_ptr, g_ctx);
    cudaGetSymbolAddress((void**)&xtf_ptr, g_xtf);
    cudaGetSymbolAddress((void**)&wt_ptr,  g_Wt);
    cudaGetSymbolAddress((void**)&wpt_ptr, g_Wpt);

    cudaFuncSetAttribute(tf32_gemm<false>,
                         cudaFuncAttributeMaxDynamicSharedMemorySize, SMEM_DYN);
    cudaFuncSetAttribute(tf32_gemm<true>,
                         cudaFuncAttributeMaxDynamicSharedMemorySize, SMEM_DYN);

    transpose_kernel<<<dim3(3 * CDIM / 32, CDIM / 32), 256>>>(W_qkv, wt_ptr);
    round_kernel<<<1024, 256>>>((const float4*)W_proj, (float4*)wpt_ptr,
                                CDIM * CDIM / 4);
    round_kernel<<<8192, 256>>>((const float4*)x, (float4*)xtf_ptr,
                                MTOK * CDIM / 4);

    tf32_gemm<false><<<dim3(3 * CDIM / BN, MTOK / BM), 256, SMEM_DYN>>>(
        xtf_ptr, wt_ptr, nullptr, qkv_ptr, 3 * CDIM);

    attn_core_kernel<<<BDIM * HDIM / 8, 256>>>(W_E, W_F);
    attn_sel_kernel<<<BDIM * HDIM / 8, 256>>>(attn_sel);

    tf32_gemm<true><<<dim3(CDIM / BN, MTOK / BM), 256, SMEM_DYN>>>(
        ctx_ptr, wpt_ptr, b_proj, out, CDIM);
}

// round 15
// speedup vs baseline: 1.0936x; 1.0936x over previous
#include <cuda_runtime.h>

// ---------------------------------------------------------------------------
// Linformer block via mma.sync tf32 (HMMA; compute_103 PTX target).
// R15: R13 GEMM (128x128, 8 warps 4m x 2n, LDSM.x4, RS=36) + 3-stage
// cp.async (2-chunk prefetch) while KEEPING 2 CTAs/SM (216KB smem/SM).
// x rounded in-loop in GEMM1 (round pass deleted).
// ---------------------------------------------------------------------------

#define BDIM  8192
#define NTOK  4
#define CDIM  1024
#define HDIM  16
#define DDIM  64
#define PDIM  4
#define MTOK  (BDIM * NTOK)
#define SCALE_F 0.125f

__device__ float g_qkv[(size_t)MTOK * 3 * CDIM];
__device__ float g_ctx[(size_t)MTOK * CDIM];
__device__ float g_Wt [(size_t)3 * CDIM * CDIM];
__device__ float g_Wpt[(size_t)CDIM * CDIM];

// ------------------------------ GEMM config --------------------------------
#define BM 128
#define BN 128
#define BKC 32
#define NCH (CDIM / BKC)
#define RS 36                              // 144B rows: LDSM/STS conflict-free
#define STAGE_FLOATS (256 * RS)
#define STAGE_BYTES  (STAGE_FLOATS * 4)    // 36864
#define NSTAGE 3
#define SMEM_DYN (NSTAGE * STAGE_BYTES)    // 110592 -> 2 CTAs/SM (216KB)

__device__ __forceinline__ unsigned smem_u32(const void* p) {
    unsigned a;
    asm("{ .reg .u64 t; cvta.to.shared.u64 t, %1; cvt.u32.u64 %0, t; }"
        : "=r"(a) : "l"(p));
    return a;
}
__device__ __forceinline__ void cp16(unsigned saddr, const float* g) {
    asm volatile("cp.async.cg.shared.global [%0], [%1], 16;"
                 :: "r"(saddr), "l"(g) : "memory");
}
__device__ __forceinline__ void cp_commit() {
    asm volatile("cp.async.commit_group;" ::: "memory");
}
template<int N_>
__device__ __forceinline__ void cp_wait() {
    asm volatile("cp.async.wait_group %0;" :: "n"(N_) : "memory");
}
__device__ __forceinline__ unsigned f2tf(float f) {
    unsigned u; asm("cvt.rna.tf32.f32 %0, %1;" : "=r"(u) : "f"(f)); return u;
}
__device__ __forceinline__ float f2tf_f(float f) {
    return __uint_as_float(f2tf(f));
}
__device__ __forceinline__ unsigned f2tf_u(unsigned u) {
    return f2tf(__uint_as_float(u));
}
__device__ __forceinline__ void ldsm4(unsigned& r0, unsigned& r1,
                                      unsigned& r2, unsigned& r3, unsigned a) {
    asm volatile("ldmatrix.sync.aligned.m8n8.x4.shared.b16 {%0,%1,%2,%3}, [%4];"
                 : "=r"(r0), "=r"(r1), "=r"(r2), "=r"(r3) : "r"(a));
}
__device__ __forceinline__ void mma_tf32(float* d, const unsigned* a,
                                         const unsigned* b) {
    asm volatile(
        "mma.sync.aligned.m16n8k8.row.col.f32.tf32.tf32.f32 "
        "{%0,%1,%2,%3}, {%4,%5,%6,%7}, {%8,%9}, {%0,%1,%2,%3};"
        : "+f"(d[0]), "+f"(d[1]), "+f"(d[2]), "+f"(d[3])
        : "r"(a[0]), "r"(a[1]), "r"(a[2]), "r"(a[3]), "r"(b[0]), "r"(b[1]));
}

// ---------------------------------------------------------------------------
// C[M,Ncols] = A[M,1024] * B^T (+bias); B pre-rounded tf32.
// CVTA: round A fragments post-LDSM (A raw fp32 in gmem).
// 128x128 tile, 8 warps (4m x 2n), 3-stage cp.async, 1 barrier/chunk.
// ---------------------------------------------------------------------------
template<bool BIAS, bool CVTA>
__global__ __launch_bounds__(256, 2)
void tf32_gemm(const float* __restrict__ A, const float* __restrict__ B,
               const float* __restrict__ bias, float* __restrict__ C, int Ncols)
{
    extern __shared__ float smf[];
    const unsigned sb = smem_u32(smf);
    const int tid = threadIdx.x;
    const int m0 = blockIdx.y * BM;
    const int n0 = blockIdx.x * BN;

    const int w  = tid >> 5;
    const int wm = w & 3;
    const int wn = w >> 2;
    const int ln = tid & 31;
    const int g  = ln >> 2;
    const int q  = ln & 3;

    const float* gA[4]; unsigned sA[4];
    const float* gB[4]; unsigned sB[4];
    #pragma unroll
    for (int i = 0; i < 4; i++) {
        int idx = tid + i * 256;
        int row = idx >> 3, seg = idx & 7;
        gA[i] = A + (size_t)(m0 + row) * CDIM + seg * 4;
        sA[i] = sb + (row * RS + seg * 4) * 4;
        gB[i] = B + (size_t)(n0 + row) * CDIM + seg * 4;
        sB[i] = sb + ((128 + row) * RS + seg * 4) * 4;
    }

    #define ISSUE(ch) do { unsigned so = ((ch) % NSTAGE) * STAGE_BYTES;       \
        int ko = (ch) * BKC;                                                  \
        _Pragma("unroll") for (int i = 0; i < 4; i++) {                       \
            cp16(sA[i] + so, gA[i] + ko);                                     \
            cp16(sB[i] + so, gB[i] + ko); }                                    \
        cp_commit(); } while (0)

    float acc[2][8][4];
    #pragma unroll
    for (int mf = 0; mf < 2; mf++)
        #pragma unroll
        for (int nf = 0; nf < 8; nf++)
            #pragma unroll
            for (int i = 0; i < 4; i++) acc[mf][nf][i] = 0.f;

    ISSUE(0);
    ISSUE(1);

    // LDSM per-lane base addresses (stage 0, kk=0)
    const unsigned aA = sb + ((wm * 32 + (ln & 15)) * RS) * 4 + ((ln & 16) ? 16 : 0);
    const unsigned aB = sb + ((128 + wn * 64 + (ln & 7) + ((ln & 16) ? 8 : 0)) * RS) * 4
                        + ((ln & 8) ? 16 : 0);

    for (int s = 0; s < NCH; s++) {
        // outstanding groups: {s, s+1}; keep newest, drain group s
        if (s < NCH - 1) cp_wait<1>(); else cp_wait<0>();
        __syncthreads();
        if (s + 2 < NCH) ISSUE(s + 2);   // stage (s+2)%3 last read at chunk s-1

        const unsigned sof = (s % NSTAGE) * STAGE_BYTES;

        #pragma unroll
        for (int kk = 0; kk < 4; kk++) {
            const unsigned ko = sof + kk * 32;
            unsigned a0[4], a1[4], br[4][4];
            ldsm4(a0[0], a0[1], a0[2], a0[3], aA + ko);                 // rows 0-15
            ldsm4(a1[0], a1[1], a1[2], a1[3], aA + ko + 16 * RS * 4);   // rows 16-31
            if (CVTA) {
                #pragma unroll
                for (int i = 0; i < 4; i++) {
                    a0[i] = f2tf_u(a0[i]);
                    a1[i] = f2tf_u(a1[i]);
                }
            }
            #pragma unroll
            for (int j = 0; j < 4; j++)
                ldsm4(br[j][0], br[j][1], br[j][2], br[j][3],
                      aB + ko + j * (16 * RS * 4));
            #pragma unroll
            for (int j = 0; j < 4; j++) {
                mma_tf32(acc[0][2 * j],     a0, &br[j][0]);
                mma_tf32(acc[0][2 * j + 1], a0, &br[j][2]);
                mma_tf32(acc[1][2 * j],     a1, &br[j][0]);
                mma_tf32(acc[1][2 * j + 1], a1, &br[j][2]);
            }
        }
    }

    const int mw = m0 + wm * 32 + g;
    const int nw = n0 + wn * 64 + 2 * q;
    #pragma unroll
    for (int mf = 0; mf < 2; mf++) {
        #pragma unroll
        for (int nf = 0; nf < 8; nf++) {
            int col = nw + nf * 8;
            float b0 = 0.f, b1 = 0.f;
            if (BIAS) { b0 = __ldg(bias + col); b1 = __ldg(bias + col + 1); }
            float* p0 = C + (size_t)(mw + mf * 16) * Ncols + col;
            float* p1 = p0 + (size_t)8 * Ncols;
            p0[0] = acc[mf][nf][0] + b0;  p0[1] = acc[mf][nf][1] + b1;
            p1[0] = acc[mf][nf][2] + b0;  p1[1] = acc[mf][nf][3] + b1;
        }
    }
    #undef ISSUE
}

// ---------------------------------------------------------------------------
// W_qkv transpose + tf32 round
// ---------------------------------------------------------------------------
__global__ __launch_bounds__(256)
void transpose_kernel(const float* __restrict__ in, float* __restrict__ out)
{
    __shared__ float t[32][33];
    int bx = blockIdx.x * 32, by = blockIdx.y * 32;
    int x = threadIdx.x & 31, y = threadIdx.x >> 5;
    #pragma unroll
    for (int i = 0; i < 32; i += 8)
        t[y + i][x] = f2tf_f(in[(size_t)(by + y + i) * (3 * CDIM) + bx + x]);
    __syncthreads();
    #pragma unroll
    for (int i = 0; i < 32; i += 8)
        out[(size_t)(bx + y + i) * CDIM + by + x] = t[x][y + i];
}

__global__ __launch_bounds__(256)
void round_kernel(const float4* __restrict__ in, float4* __restrict__ out, int n4)
{
    for (int i = blockIdx.x * blockDim.x + threadIdx.x; i < n4;
         i += gridDim.x * blockDim.x) {
        float4 v = in[i];
        v.x = f2tf_f(v.x); v.y = f2tf_f(v.y);
        v.z = f2tf_f(v.z); v.w = f2tf_f(v.w);
        out[i] = v;
    }
}

// ---------------------------------------------------------------------------
// Middle main: one warp per (b,h); lane owns d = {2*lane, 2*lane+1}.
// ---------------------------------------------------------------------------
__global__ __launch_bounds__(256)
void attn_core_kernel(const float* __restrict__ W_E, const float* __restrict__ W_F)
{
    const int wglob = blockIdx.x * 8 + (threadIdx.x >> 5);
    const int b = wglob >> 4;
    const int h = wglob & 15;
    const int lane = threadIdx.x & 31;

    const float* base = g_qkv + (size_t)b * NTOK * 3 * CDIM + h * DDIM + 2 * lane;

    float2 qv[NTOK], kv[NTOK], vv[NTOK];
    #pragma unroll
    for (int n = 0; n < NTOK; n++) {
        const float* r = base + (size_t)n * 3 * CDIM;
        qv[n] = *reinterpret_cast<const float2*>(r);
        kv[n] = *reinterpret_cast<const float2*>(r + CDIM);
        vv[n] = *reinterpret_cast<const float2*>(r + 2 * CDIM);
    }

    float we[16], wf[16];
    #pragma unroll
    for (int i = 0; i < 16; i++) { we[i] = __ldg(W_E + i); wf[i] = __ldg(W_F + i); }

    float2 kl[PDIM], vl[PDIM];
    #pragma unroll
    for (int p = 0; p < PDIM; p++) {
        kl[p].x = kl[p].y = vl[p].x = vl[p].y = 0.f;
        #pragma unroll
        for (int n = 0; n < NTOK; n++) {
            kl[p].x += kv[n].x * we[p * 4 + n];
            kl[p].y += kv[n].y * we[p * 4 + n];
            vl[p].x += vv[n].x * wf[p * 4 + n];
            vl[p].y += vv[n].y * wf[p * 4 + n];
        }
    }

    float lg[16];
    #pragma unroll
    for (int n = 0; n < NTOK; n++)
        #pragma unroll
        for (int p = 0; p < PDIM; p++)
            lg[n * 4 + p] = qv[n].x * kl[p].x + qv[n].y * kl[p].y;
    #pragma unroll
    for (int off = 16; off >= 1; off >>= 1)
        #pragma unroll
        for (int i = 0; i < 16; i++)
            lg[i] += __shfl_xor_sync(0xFFFFFFFFu, lg[i], off);

    float aw[16];
    #pragma unroll
    for (int n = 0; n < NTOK; n++) {
        float l0 = lg[n * 4] * SCALE_F, l1 = lg[n * 4 + 1] * SCALE_F;
        float l2 = lg[n * 4 + 2] * SCALE_F, l3 = lg[n * 4 + 3] * SCALE_F;
        float mx = fmaxf(fmaxf(l0, l1), fmaxf(l2, l3));
        float e0 = __expf(l0 - mx), e1 = __expf(l1 - mx);
        float e2 = __expf(l2 - mx), e3 = __expf(l3 - mx);
        float inv = 1.f / (e0 + e1 + e2 + e3);
        aw[n * 4] = e0 * inv; aw[n * 4 + 1] = e1 * inv;
        aw[n * 4 + 2] = e2 * inv; aw[n * 4 + 3] = e3 * inv;
    }

    float* cbase = g_ctx + (size_t)b * NTOK * CDIM + h * DDIM + 2 * lane;
    #pragma unroll
    for (int n = 0; n < NTOK; n++) {
        float ox = 0.f, oy = 0.f;
        #pragma unroll
        for (int p = 0; p < PDIM; p++) {
            ox += aw[n * 4 + p] * vl[p].x;
            oy += aw[n * 4 + p] * vl[p].y;
        }
        float2 o; o.x = f2tf_f(ox); o.y = f2tf_f(oy);
        *reinterpret_cast<float2*>(cbase + (size_t)n * CDIM) = o;
    }
}

// ---------------------------------------------------------------------------
// attn_sel: one warp per (b,h)
// ---------------------------------------------------------------------------
__global__ __launch_bounds__(256)
void attn_sel_kernel(float* __restrict__ attn_sel)
{
    const int wglob = blockIdx.x * 8 + (threadIdx.x >> 5);
    const int b = wglob >> 4;
    const int h = wglob & 15;
    const int lane = threadIdx.x & 31;

    const float* base = g_qkv + (size_t)b * NTOK * 3 * CDIM;
    float2 qv = *reinterpret_cast<const float2*>(
        base + (size_t)1 * 3 * CDIM + h * DDIM + 2 * lane);

    const float* k2 = base + (size_t)2 * 3 * CDIM + CDIM + 2 * lane;
    float s[16];
    #pragma unroll
    for (int gg = 0; gg < 16; gg++) {
        float2 kv = *reinterpret_cast<const float2*>(k2 + gg * DDIM);
        s[gg] = qv.x * kv.x + qv.y * kv.y;
    }
    #pragma unroll
    for (int off = 16; off >= 1; off >>= 1)
        #pragma unroll
        for (int i = 0; i < 16; i++)
            s[i] += __shfl_xor_sync(0xFFFFFFFFu, s[i], off);

    if (lane < 16) {
        float v = s[lane] * SCALE_F;
        attn_sel[((size_t)b * HDIM + h) * HDIM + lane] = 1.f / (1.f + __expf(-v));
    }
}

// ---------------------------------------------------------------------------
extern "C" void kernel_launch(void* const* d_in, const int* in_sizes, int n_in,
                              void* d_out, int out_size)
{
    (void)in_sizes; (void)n_in; (void)out_size;
    const float* x      = (const float*)d_in[0];
    const float* W_qkv  = (const float*)d_in[1];
    const float* W_proj = (const float*)d_in[2];
    const float* b_proj = (const float*)d_in[3];
    const float* W_E    = (const float*)d_in[4];
    const float* W_F    = (const float*)d_in[5];

    float* out      = (float*)d_out;
    float* attn_sel = out + (size_t)MTOK * CDIM;

    float *qkv_ptr, *ctx_ptr, *wt_ptr, *wpt_ptr;
    cudaGetSymbolAddress((void**)&qkv_ptr, g_qkv);
    cudaGetSymbolAddress((void**)&ctx_ptr, g_ctx);
    cudaGetSymbolAddress((void**)&wt_ptr,  g_Wt);
    cudaGetSymbolAddress((void**)&wpt_ptr, g_Wpt);

    cudaFuncSetAttribute((const void*)tf32_gemm<false, true>,
                         cudaFuncAttributeMaxDynamicSharedMemorySize, SMEM_DYN);
    cudaFuncSetAttribute((const void*)tf32_gemm<true, false>,
                         cudaFuncAttributeMaxDynamicSharedMemorySize, SMEM_DYN);

    // Weight prep (x consumed raw; ctx pre-rounded by middle kernel)
    transpose_kernel<<<dim3(3 * CDIM / 32, CDIM / 32), 256>>>(W_qkv, wt_ptr);
    round_kernel<<<1024, 256>>>((const float4*)W_proj, (float4*)wpt_ptr,
                                CDIM * CDIM / 4);

    // K1: qkv = x @ Wt^T   (A rounded in-loop)
    tf32_gemm<false, true><<<dim3(3 * CDIM / BN, MTOK / BM), 256, SMEM_DYN>>>(
        x, wt_ptr, nullptr, qkv_ptr, 3 * CDIM);

    // K2: middle (warp-parallel, smem-free)
    attn_core_kernel<<<BDIM * HDIM / 8, 256>>>(W_E, W_F);
    attn_sel_kernel<<<BDIM * HDIM / 8, 256>>>(attn_sel);

    // K3: out = ctx @ Wpt^T + b
    tf32_gemm<true, false><<<dim3(CDIM / BN, MTOK / BM), 256, SMEM_DYN>>>(
        ctx_ptr, wpt_ptr, b_proj, out, CDIM);
}

// round 16
// speedup vs baseline: 1.8379x; 1.6806x over previous
#include <cuda_runtime.h>
#include <cuda_fp16.h>

// ---------------------------------------------------------------------------
// Linformer block via mma.sync fp16 HMMA (m16n8k16, fp32 accum).
// R16: operands converted to fp16 (same 11-bit mantissa as tf32; fp32 accum
// => same error profile), halving tensor instructions and all operand bytes.
// GEMM structure = proven R13/R15 shell: 128x128 tile, 8 warps (4m x 2n),
// LDSM.x4, 144B rows, 3-stage cp.async, 2 CTAs/SM, 1 barrier/chunk.
// ---------------------------------------------------------------------------

#define BDIM  8192
#define NTOK  4
#define CDIM  1024
#define HDIM  16
#define DDIM  64
#define PDIM  4
#define MTOK  (BDIM * NTOK)
#define SCALE_F 0.125f

__device__ float  g_qkv[(size_t)MTOK * 3 * CDIM];      // fp32 GEMM1 output
__device__ __half g_xh [(size_t)MTOK * CDIM];          // x in fp16
__device__ __half g_ctxh[(size_t)MTOK * CDIM];         // ctx in fp16
__device__ __half g_Wth[(size_t)3 * CDIM * CDIM];      // W_qkv^T fp16 [3072,1024]
__device__ __half g_Wph[(size_t)CDIM * CDIM];          // W_proj fp16 [1024,1024]

// ------------------------------ GEMM config --------------------------------
#define BM 128
#define BN 128
#define BKC 64                              // halves per chunk (128 B/row)
#define NCH (CDIM / BKC)                    // 16 chunks
#define ROWB 144                            // bytes per smem row (72 halves)
#define STAGE_BYTES (256 * ROWB)            // 36864 (128 A rows + 128 B rows)
#define NSTAGE 3
#define SMEM_DYN (NSTAGE * STAGE_BYTES)     // 110592 -> 2 CTAs/SM

__device__ __forceinline__ unsigned smem_u32(const void* p) {
    unsigned a;
    asm("{ .reg .u64 t; cvta.to.shared.u64 t, %1; cvt.u32.u64 %0, t; }"
        : "=r"(a) : "l"(p));
    return a;
}
__device__ __forceinline__ void cp16(unsigned saddr, const void* g) {
    asm volatile("cp.async.cg.shared.global [%0], [%1], 16;"
                 :: "r"(saddr), "l"(g) : "memory");
}
__device__ __forceinline__ void cp_commit() {
    asm volatile("cp.async.commit_group;" ::: "memory");
}
template<int N_>
__device__ __forceinline__ void cp_wait() {
    asm volatile("cp.async.wait_group %0;" :: "n"(N_) : "memory");
}
__device__ __forceinline__ void ldsm4(unsigned& r0, unsigned& r1,
                                      unsigned& r2, unsigned& r3, unsigned a) {
    asm volatile("ldmatrix.sync.aligned.m8n8.x4.shared.b16 {%0,%1,%2,%3}, [%4];"
                 : "=r"(r0), "=r"(r1), "=r"(r2), "=r"(r3) : "r"(a));
}
__device__ __forceinline__ void mma_f16(float* d, const unsigned* a,
                                        const unsigned* b) {
    asm volatile(
        "mma.sync.aligned.m16n8k16.row.col.f32.f16.f16.f32 "
        "{%0,%1,%2,%3}, {%4,%5,%6,%7}, {%8,%9}, {%0,%1,%2,%3};"
        : "+f"(d[0]), "+f"(d[1]), "+f"(d[2]), "+f"(d[3])
        : "r"(a[0]), "r"(a[1]), "r"(a[2]), "r"(a[3]), "r"(b[0]), "r"(b[1]));
}

// ---------------------------------------------------------------------------
// C[M,Ncols] = A[M,1024] * B^T (+bias); A,B fp16, B stored [Ncols,1024].
// 128x128 tile, 8 warps (4m x 2n), warp tile 32x64, 3-stage cp.async.
// Per chunk: 4 k16-slices; per slice: 2 A-LDSM.x4, 4 B-LDSM.x4, 16 MMA.
// ---------------------------------------------------------------------------
template<bool BIAS>
__global__ __launch_bounds__(256, 2)
void h_gemm(const __half* __restrict__ A, const __half* __restrict__ B,
            const float* __restrict__ bias, float* __restrict__ C, int Ncols)
{
    extern __shared__ char smc[];
    const unsigned sb = smem_u32(smc);
    const int tid = threadIdx.x;
    const int m0 = blockIdx.y * BM;
    const int n0 = blockIdx.x * BN;

    const int w  = tid >> 5;
    const int wm = w & 3;
    const int wn = w >> 2;
    const int ln = tid & 31;
    const int g  = ln >> 2;
    const int q  = ln & 3;

    // cp.async: per chunk 128 rows x 128B for A and B -> 8 x 16B per thread
    const __half* gA[4]; unsigned sA[4];
    const __half* gB[4]; unsigned sB[4];
    #pragma unroll
    for (int i = 0; i < 4; i++) {
        int idx = tid + i * 256;
        int row = idx >> 3, seg = idx & 7;
        gA[i] = A + (size_t)(m0 + row) * CDIM + seg * 8;
        sA[i] = sb + row * ROWB + seg * 16;
        gB[i] = B + (size_t)(n0 + row) * CDIM + seg * 8;
        sB[i] = sb + (128 + row) * ROWB + seg * 16;
    }

    #define ISSUE(ch) do { unsigned so = ((ch) % NSTAGE) * STAGE_BYTES;       \
        int ko = (ch) * BKC;                                                  \
        _Pragma("unroll") for (int i = 0; i < 4; i++) {                       \
            cp16(sA[i] + so, gA[i] + ko);                                     \
            cp16(sB[i] + so, gB[i] + ko); }                                    \
        cp_commit(); } while (0)

    float acc[2][8][4];
    #pragma unroll
    for (int mf = 0; mf < 2; mf++)
        #pragma unroll
        for (int nf = 0; nf < 8; nf++)
            #pragma unroll
            for (int i = 0; i < 4; i++) acc[mf][nf][i] = 0.f;

    ISSUE(0);
    ISSUE(1);

    // LDSM lane bases (stage 0, slice 0):
    // A m16k16: lanes 0-15 rows (ln&15) col 0; lanes 16-31 same rows col 8h.
    const unsigned aA = sb + (wm * 32 + (ln & 15)) * ROWB + ((ln & 16) ? 16 : 0);
    // B n16k16 tiles: rows n, (ln&16)?+8 n; (ln&8)?+8h k.
    const unsigned aB = sb + (128 + wn * 64 + (ln & 7) + ((ln & 16) ? 8 : 0)) * ROWB
                        + ((ln & 8) ? 16 : 0);

    for (int s = 0; s < NCH; s++) {
        if (s < NCH - 1) cp_wait<1>(); else cp_wait<0>();
        __syncthreads();
        if (s + 2 < NCH) ISSUE(s + 2);   // stage (s+2)%3 last read at chunk s-1

        const unsigned sof = (s % NSTAGE) * STAGE_BYTES;

        #pragma unroll
        for (int kk = 0; kk < 4; kk++) {         // k16 per slice
            const unsigned ko = sof + kk * 32;   // 16 halves = 32 B
            unsigned a0[4], a1[4], br[4][4];
            ldsm4(a0[0], a0[1], a0[2], a0[3], aA + ko);                  // m rows 0-15
            ldsm4(a1[0], a1[1], a1[2], a1[3], aA + ko + 16 * ROWB);      // m rows 16-31
            #pragma unroll
            for (int j = 0; j < 4; j++)                                   // n16 groups
                ldsm4(br[j][0], br[j][1], br[j][2], br[j][3],
                      aB + ko + j * (16 * ROWB));
            #pragma unroll
            for (int j = 0; j < 4; j++) {
                mma_f16(acc[0][2 * j],     a0, &br[j][0]);   // n 0-7 of group
                mma_f16(acc[0][2 * j + 1], a0, &br[j][2]);   // n 8-15
                mma_f16(acc[1][2 * j],     a1, &br[j][0]);
                mma_f16(acc[1][2 * j + 1], a1, &br[j][2]);
            }
        }
    }

    // Epilogue: same fp32 D layout as tf32 m16n8
    const int mw = m0 + wm * 32 + g;
    const int nw = n0 + wn * 64 + 2 * q;
    #pragma unroll
    for (int mf = 0; mf < 2; mf++) {
        #pragma unroll
        for (int nf = 0; nf < 8; nf++) {
            int col = nw + nf * 8;
            float b0 = 0.f, b1 = 0.f;
            if (BIAS) { b0 = __ldg(bias + col); b1 = __ldg(bias + col + 1); }
            float* p0 = C + (size_t)(mw + mf * 16) * Ncols + col;
            float* p1 = p0 + (size_t)8 * Ncols;
            p0[0] = acc[mf][nf][0] + b0;  p0[1] = acc[mf][nf][1] + b1;
            p1[0] = acc[mf][nf][2] + b0;  p1[1] = acc[mf][nf][3] + b1;
        }
    }
    #undef ISSUE
}

// ---------------------------------------------------------------------------
// W_qkv transpose + fp16 convert: [1024,3072] fp32 -> [3072,1024] half
// ---------------------------------------------------------------------------
__global__ __launch_bounds__(256)
void transpose_h_kernel(const float* __restrict__ in, __half* __restrict__ out)
{
    __shared__ float t[32][33];
    int bx = blockIdx.x * 32, by = blockIdx.y * 32;
    int x = threadIdx.x & 31, y = threadIdx.x >> 5;
    #pragma unroll
    for (int i = 0; i < 32; i += 8)
        t[y + i][x] = in[(size_t)(by + y + i) * (3 * CDIM) + bx + x];
    __syncthreads();
    #pragma unroll
    for (int i = 0; i < 32; i += 8)
        out[(size_t)(bx + y + i) * CDIM + by + x] = __float2half_rn(t[x][y + i]);
}

// ---------------------------------------------------------------------------
// fp32 -> fp16 convert (float4 -> 2x half2)
// ---------------------------------------------------------------------------
__global__ __launch_bounds__(256)
void cvt_half_kernel(const float4* __restrict__ in, __half2* __restrict__ out,
                     int n4)
{
    for (int i = blockIdx.x * blockDim.x + threadIdx.x; i < n4;
         i += gridDim.x * blockDim.x) {
        float4 v = in[i];
        out[2 * i]     = __floats2half2_rn(v.x, v.y);
        out[2 * i + 1] = __floats2half2_rn(v.z, v.w);
    }
}

// ---------------------------------------------------------------------------
// Middle main: one warp per (b,h); lane owns d = {2*lane, 2*lane+1}.
// ctx written directly as fp16 (GEMM2 A operand).
// ---------------------------------------------------------------------------
__global__ __launch_bounds__(256)
void attn_core_kernel(const float* __restrict__ W_E, const float* __restrict__ W_F)
{
    const int wglob = blockIdx.x * 8 + (threadIdx.x >> 5);
    const int b = wglob >> 4;
    const int h = wglob & 15;
    const int lane = threadIdx.x & 31;

    const float* base = g_qkv + (size_t)b * NTOK * 3 * CDIM + h * DDIM + 2 * lane;

    float2 qv[NTOK], kv[NTOK], vv[NTOK];
    #pragma unroll
    for (int n = 0; n < NTOK; n++) {
        const float* r = base + (size_t)n * 3 * CDIM;
        qv[n] = *reinterpret_cast<const float2*>(r);
        kv[n] = *reinterpret_cast<const float2*>(r + CDIM);
        vv[n] = *reinterpret_cast<const float2*>(r + 2 * CDIM);
    }

    float we[16], wf[16];
    #pragma unroll
    for (int i = 0; i < 16; i++) { we[i] = __ldg(W_E + i); wf[i] = __ldg(W_F + i); }

    float2 kl[PDIM], vl[PDIM];
    #pragma unroll
    for (int p = 0; p < PDIM; p++) {
        kl[p].x = kl[p].y = vl[p].x = vl[p].y = 0.f;
        #pragma unroll
        for (int n = 0; n < NTOK; n++) {
            kl[p].x += kv[n].x * we[p * 4 + n];
            kl[p].y += kv[n].y * we[p * 4 + n];
            vl[p].x += vv[n].x * wf[p * 4 + n];
            vl[p].y += vv[n].y * wf[p * 4 + n];
        }
    }

    float lg[16];
    #pragma unroll
    for (int n = 0; n < NTOK; n++)
        #pragma unroll
        for (int p = 0; p < PDIM; p++)
            lg[n * 4 + p] = qv[n].x * kl[p].x + qv[n].y * kl[p].y;
    #pragma unroll
    for (int off = 16; off >= 1; off >>= 1)
        #pragma unroll
        for (int i = 0; i < 16; i++)
            lg[i] += __shfl_xor_sync(0xFFFFFFFFu, lg[i], off);

    float aw[16];
    #pragma unroll
    for (int n = 0; n < NTOK; n++) {
        float l0 = lg[n * 4] * SCALE_F, l1 = lg[n * 4 + 1] * SCALE_F;
        float l2 = lg[n * 4 + 2] * SCALE_F, l3 = lg[n * 4 + 3] * SCALE_F;
        float mx = fmaxf(fmaxf(l0, l1), fmaxf(l2, l3));
        float e0 = __expf(l0 - mx), e1 = __expf(l1 - mx);
        float e2 = __expf(l2 - mx), e3 = __expf(l3 - mx);
        float inv = 1.f / (e0 + e1 + e2 + e3);
        aw[n * 4] = e0 * inv; aw[n * 4 + 1] = e1 * inv;
        aw[n * 4 + 2] = e2 * inv; aw[n * 4 + 3] = e3 * inv;
    }

    __half* cbase = g_ctxh + (size_t)b * NTOK * CDIM + h * DDIM + 2 * lane;
    #pragma unroll
    for (int n = 0; n < NTOK; n++) {
        float ox = 0.f, oy = 0.f;
        #pragma unroll
        for (int p = 0; p < PDIM; p++) {
            ox += aw[n * 4 + p] * vl[p].x;
            oy += aw[n * 4 + p] * vl[p].y;
        }
        *reinterpret_cast<__half2*>(cbase + (size_t)n * CDIM) =
            __floats2half2_rn(ox, oy);
    }
}

// ---------------------------------------------------------------------------
// attn_sel: one warp per (b,h)
// ---------------------------------------------------------------------------
__global__ __launch_bounds__(256)
void attn_sel_kernel(float* __restrict__ attn_sel)
{
    const int wglob = blockIdx.x * 8 + (threadIdx.x >> 5);
    const int b = wglob >> 4;
    const int h = wglob & 15;
    const int lane = threadIdx.x & 31;

    const float* base = g_qkv + (size_t)b * NTOK * 3 * CDIM;
    float2 qv = *reinterpret_cast<const float2*>(
        base + (size_t)1 * 3 * CDIM + h * DDIM + 2 * lane);

    const float* k2 = base + (size_t)2 * 3 * CDIM + CDIM + 2 * lane;
    float s[16];
    #pragma unroll
    for (int gg = 0; gg < 16; gg++) {
        float2 kv = *reinterpret_cast<const float2*>(k2 + gg * DDIM);
        s[gg] = qv.x * kv.x + qv.y * kv.y;
    }
    #pragma unroll
    for (int off = 16; off >= 1; off >>= 1)
        #pragma unroll
        for (int i = 0; i < 16; i++)
            s[i] += __shfl_xor_sync(0xFFFFFFFFu, s[i], off);

    if (lane < 16) {
        float v = s[lane] * SCALE_F;
        attn_sel[((size_t)b * HDIM + h) * HDIM + lane] = 1.f / (1.f + __expf(-v));
    }
}

// ---------------------------------------------------------------------------
extern "C" void kernel_launch(void* const* d_in, const int* in_sizes, int n_in,
                              void* d_out, int out_size)
{
    (void)in_sizes; (void)n_in; (void)out_size;
    const float* x      = (const float*)d_in[0];
    const float* W_qkv  = (const float*)d_in[1];
    const float* W_proj = (const float*)d_in[2];
    const float* b_proj = (const float*)d_in[3];
    const float* W_E    = (const float*)d_in[4];
    const float* W_F    = (const float*)d_in[5];

    float* out      = (float*)d_out;
    float* attn_sel = out + (size_t)MTOK * CDIM;

    float *qkv_ptr;
    __half *xh_ptr, *ctxh_ptr, *wth_ptr, *wph_ptr;
    cudaGetSymbolAddress((void**)&qkv_ptr,  g_qkv);
    cudaGetSymbolAddress((void**)&xh_ptr,   g_xh);
    cudaGetSymbolAddress((void**)&ctxh_ptr, g_ctxh);
    cudaGetSymbolAddress((void**)&wth_ptr,  g_Wth);
    cudaGetSymbolAddress((void**)&wph_ptr,  g_Wph);

    cudaFuncSetAttribute(h_gemm<false>,
                         cudaFuncAttributeMaxDynamicSharedMemorySize, SMEM_DYN);
    cudaFuncSetAttribute(h_gemm<true>,
                         cudaFuncAttributeMaxDynamicSharedMemorySize, SMEM_DYN);

    // Operand conversion to fp16
    transpose_h_kernel<<<dim3(3 * CDIM / 32, CDIM / 32), 256>>>(W_qkv, wth_ptr);
    cvt_half_kernel<<<1024, 256>>>((const float4*)W_proj, (__half2*)wph_ptr,
                                   CDIM * CDIM / 4);
    cvt_half_kernel<<<8192, 256>>>((const float4*)x, (__half2*)xh_ptr,
                                   MTOK * CDIM / 4);

    // K1: qkv = x @ W_qkv^T(half)
    h_gemm<false><<<dim3(3 * CDIM / BN, MTOK / BM), 256, SMEM_DYN>>>(
        xh_ptr, wth_ptr, nullptr, qkv_ptr, 3 * CDIM);

    // K2: middle (warp-parallel, smem-free; ctx -> fp16)
    attn_core_kernel<<<BDIM * HDIM / 8, 256>>>(W_E, W_F);
    attn_sel_kernel<<<BDIM * HDIM / 8, 256>>>(attn_sel);

    // K3: out = ctx @ W_proj^T + b
    h_gemm<true><<<dim3(CDIM / BN, MTOK / BM), 256, SMEM_DYN>>>(
        ctxh_ptr, wph_ptr, b_proj, out, CDIM);
}